// round 12
// baseline (speedup 1.0000x reference)
#include <cuda_runtime.h>
#include <cuda_bf16.h>
#include <math.h>

#define BB 4
#define HH 512
#define WW 512
#define NPIX (BB*HH*WW)
#define TW 32
#define TH 8

#define TAUc   0.01f
#define RHOc   1.99f
#define SIGMAc 1.3888888888888888f   // 1/0.01/72

// Double-buffered state. u2: 4x bf16 (uint2). r2: 2x bf16 (u32). x2: fp32.
typedef uint2 U2raw;
__device__ __align__(16) float    g_x2a[NPIX], g_x2b[NPIX];
__device__ __align__(16) unsigned g_r2a[NPIX], g_r2b[NPIX];
__device__ __align__(16) U2raw    g_u2a[NPIX], g_u2b[NPIX];

static __device__ __forceinline__ float2 bf2unpack(unsigned r) {
    return __bfloat1622float2(*reinterpret_cast<__nv_bfloat162*>(&r));
}
static __device__ __forceinline__ unsigned bf2pack(float a, float b) {
    __nv_bfloat162 p = __floats2bfloat162_rn(a, b);
    return *reinterpret_cast<unsigned*>(&p);
}
static __device__ __forceinline__ U2raw u2pack(float a, float b, float c, float d) {
    U2raw r; r.x = bf2pack(a, b); r.y = bf2pack(c, d); return r;
}

// ---------------------------------------------------------------------------
// Fused iteration kernel v2: 32x32 tile, 3 barriers, no div/mod, v inline.
// Frames (image coords of frame element [R][C]):
//   su  [38][36] u2  at (h0+R-3, w0+C-2)
//   st  [36][35] tmp at (h0+R-2, w0+C-2)   fp32
//   sxb [35][34] xbar at (h0+R-1, w0+C-1)  fp32 ; srb same frame, bf16x2
// Zero-padding + invariants (u2.y==0 at w=0, u2.w==0 at h=H-1) make tmp
// unconditional.
// ---------------------------------------------------------------------------
template<int P>   // P=0: a->b, P=1: b->a
__global__ void __launch_bounds__(256, 6)
k_F(const float* __restrict__ y, const int* __restrict__ ths) {
    const float*    x2i = P ? g_x2b : g_x2a;
    float*          x2o = P ? g_x2a : g_x2b;
    const unsigned* r2i = P ? g_r2b : g_r2a;
    unsigned*       r2o = P ? g_r2a : g_r2b;
    const U2raw*    u2i = P ? g_u2b : g_u2a;
    U2raw*          u2o = P ? g_u2a : g_u2b;

    __shared__ uint2    su[38][36];
    __shared__ float2   st[36][35];
    __shared__ float    sxb[35][34];
    __shared__ unsigned srb[35][34];

    const int tx = threadIdx.x, ty = threadIdx.y;
    const int w0 = blockIdx.x * 32, h0 = blockIdx.y * 32, b = blockIdx.z;
    const int boff = b * HH * WW;

    // Stage 1: u2 halo load (zero-padded)
    #pragma unroll
    for (int R = ty; R < 38; R += 8) {
        #pragma unroll
        for (int C = tx; C < 36; C += 32) {
            int gh = h0 + R - 3, gw = w0 + C - 2;
            uint2 v = make_uint2(0u, 0u);
            if ((unsigned)gh < HH && (unsigned)gw < WW)
                v = __ldg(&u2i[boff + gh * WW + gw]);
            su[R][C] = v;
        }
    }
    __syncthreads();

    // Stage 2: tmp = TAU * eps2_adjoint(u2)
    #pragma unroll
    for (int R = ty; R < 36; R += 8) {
        #pragma unroll
        for (int C = tx; C < 35; C += 32) {
            uint2 cw = su[R + 1][C];
            float2 cxy = bf2unpack(cw.x), czw = bf2unpack(cw.y);
            float  dnx = bf2unpack(su[R + 2][C].x).x;
            uint2 rw = su[R + 1][C + 1];
            float2 rxy = bf2unpack(rw.x), rzw = bf2unpack(rw.y);
            float  upw = bf2unpack(su[R][C].y).y;
            st[R][C] = make_float2(TAUc * (cxy.x - dnx   - rxy.y + cxy.y),
                                   TAUc * (czw.x - rzw.x - czw.y + upw));
        }
    }
    __syncthreads();

    // Stage 3: x/xbar + r/rbar; write x2'/r2' for in-tile pixels
    const float lam1 = 0.1f * (float)__ldg(ths);
    const float itl  = 1.f / (TAUc * lam1);
    const float inv  = 1.f / (1.f + TAUc);
    #pragma unroll
    for (int R = ty; R < 35; R += 8) {
        #pragma unroll
        for (int C = tx; C < 34; C += 32) {
            int gh = h0 + R - 1, gw = w0 + C - 1;
            float xbv = 0.f;
            unsigned rbw = 0u;
            if ((unsigned)gh < HH && (unsigned)gw < WW) {
                float2 tc = st[R + 1][C + 1];
                float  tlx = st[R + 1][C].x;
                float  tuy = st[R][C + 1].y;
                float div = 0.f;
                if (gw < WW - 1) div -= tc.x;
                if (gw > 0)      div += tlx;
                if (gh < HH - 1) div -= tc.y;
                if (gh > 0)      div += tuy;
                int gi = boff + gh * WW + gw;
                float x2v = __ldg(&x2i[gi]);
                float x = (x2v - div + TAUc * __ldg(&y[gi])) * inv;
                xbv = 2.f * x - x2v;
                float2 r2v = bf2unpack(__ldg(&r2i[gi]));
                float rvx = r2v.x + tc.x, rvy = r2v.y + tc.y;
                float s = 1.f - 1.f / fmaxf(sqrtf(rvx*rvx + rvy*rvy) * itl, 1.f);
                float rx = rvx * s, ry = rvy * s;
                rbw = bf2pack(2.f * rx - r2v.x, 2.f * ry - r2v.y);
                if ((unsigned)(gh - h0) < 32u && (unsigned)(gw - w0) < 32u) {
                    x2o[gi] = x2v + RHOc * (x - x2v);
                    r2o[gi] = bf2pack(r2v.x + RHOc * (rx - r2v.x),
                                      r2v.y + RHOc * (ry - r2v.y));
                }
            }
            sxb[R][C] = xbv;
            srb[R][C] = rbw;
        }
    }
    __syncthreads();

    // Stage 4: v inline + u-prox + relaxation on the 32x32 tile
    const float lam2 = 0.15f * (float)__ldg(ths);
    const float il2 = 1.f / lam2;
    #pragma unroll
    for (int R = ty; R < 32; R += 8) {
        const int C = tx;
        const int gh = h0 + R, gw = w0 + C;
        const int r = R + 1, c = C + 1;

        const float xc  = sxb[r][c];
        const float xr  = sxb[r][c + 1];
        const float xd  = sxb[r + 1][c];
        const float xu  = sxb[r - 1][c];
        const float xur = sxb[r - 1][c + 1];
        const float xl  = sxb[r][c - 1];
        const float xdl = sxb[r + 1][c - 1];
        const float xd2 = sxb[r + 2][c];
        const float2 rbc = bf2unpack(srb[r][c]);
        const float2 rbu = bf2unpack(srb[r - 1][c]);
        const float2 rbl = bf2unpack(srb[r][c - 1]);
        const float2 rbd = bf2unpack(srb[r + 1][c]);

        const bool pR  = (gw < WW - 1);
        const bool pD  = (gh < HH - 1);
        const bool pD2 = (gh < HH - 2);

        const float v0c = (pR  ? xr  - xc : 0.f) - rbc.x;
        const float v1c = (pD  ? xd  - xc : 0.f) - rbc.y;
        const float v0u = (pR  ? xur - xu : 0.f) - rbu.x;
        const float v0l = (xc - xl) - rbl.x;
        const float v1l = (pD  ? xdl - xl : 0.f) - rbl.y;
        const float v1d = (pD2 ? xd2 - xd : 0.f) - rbd.y;

        const float G0 = v0c - v0u;
        const float G1 = (gw > 0) ? (v0c - v0l) : 0.f;
        const float G2 = v1c - v1l;
        const float G3 = pD ? (v1d - v1c) : 0.f;

        const uint2 uo = su[R + 3][C + 2];
        const float2 o0 = bf2unpack(uo.x), o1 = bf2unpack(uo.y);
        float u0 = o0.x + SIGMAc * G0;
        float u1 = o0.y + SIGMAc * G1;
        float u2c = o1.x + SIGMAc * G2;
        float u3 = o1.y + SIGMAc * G3;
        const float nrm = sqrtf(u0*u0 + u1*u1 + u2c*u2c + u3*u3);
        const float sc = 1.f / fmaxf(nrm * il2, 1.f);
        u2o[boff + gh * WW + gw] =
            u2pack(o0.x + RHOc * (u0  * sc - o0.x),
                   o0.y + RHOc * (u1  * sc - o0.y),
                   o1.x + RHOc * (u2c * sc - o1.x),
                   o1.y + RHOc * (u3  * sc - o1.y));
    }
}

// ---------------------------------------------------------------------------
// Iteration 1 (closed form: x=xbar=y, r=rbar=0, u2=0) -> buffer A.
// ---------------------------------------------------------------------------
__global__ void __launch_bounds__(TW*TH)
k_B_first(const float* __restrict__ y, const int* __restrict__ ths) {
    __shared__ float  sx[TH + 3][TW + 3];
    __shared__ float2 svv[TH + 2][TW + 2];

    const int tx = threadIdx.x, ty = threadIdx.y;
    const int tid = ty * TW + tx;
    const int w0 = blockIdx.x * TW, h0 = blockIdx.y * TH, b = blockIdx.z;
    const int boff = b * HH * WW;
    const float* xb = y + boff;

    #pragma unroll
    for (int idx = tid; idx < (TH + 3) * (TW + 2); idx += TW * TH) {
        int rr = idx / (TW + 2), cc = idx % (TW + 2);
        int gh = h0 + rr - 1, gw = w0 + cc - 1;
        float v = 0.f;
        if (gh >= 0 && gh < HH && gw >= 0 && gw < WW) v = __ldg(xb + gh * WW + gw);
        sx[rr][cc] = v;
    }
    __syncthreads();

    #pragma unroll
    for (int idx = tid; idx < (TH + 2) * (TW + 1); idx += TW * TH) {
        int R = idx / (TW + 1), C = idx % (TW + 1);
        int gh = h0 + R - 1, gw = w0 + C - 1;
        float2 v = make_float2(0.f, 0.f);
        if (gh >= 0 && gh < HH && gw >= 0 && gw < WW) {
            float xc = sx[R][C];
            float v0 = (gw < WW - 1) ? (sx[R][C + 1] - xc) : 0.f;
            float v1 = (gh < HH - 1) ? (sx[R + 1][C] - xc) : 0.f;
            v = make_float2(v0, v1);
        }
        svv[R][C] = v;
    }
    __syncthreads();

    const int h = h0 + ty, w = w0 + tx;
    const int i = boff + h * WW + w;

    float2 vc = svv[ty + 1][tx + 1];
    float2 vu = svv[ty][tx + 1];
    float2 vl = svv[ty + 1][tx];
    float2 vd = svv[ty + 2][tx + 1];

    float G0 = vc.x - vu.x;
    float G1 = (w > 0) ? (vc.x - vl.x) : 0.f;
    float G2 = vc.y - vl.y;
    float G3 = (h < HH - 1) ? (vd.y - vc.y) : 0.f;

    float u0 = SIGMAc * G0, u1 = SIGMAc * G1;
    float u2c = SIGMAc * G2, u3 = SIGMAc * G3;
    float lam2 = 0.15f * (float)__ldg(ths);
    float nrm = sqrtf(u0*u0 + u1*u1 + u2c*u2c + u3*u3);
    float sc = RHOc / fmaxf(nrm * (1.f / lam2), 1.f);
    g_u2a[i] = u2pack(u0 * sc, u1 * sc, u2c * sc, u3 * sc);
    g_x2a[i] = sx[ty + 1][tx + 1];
    g_r2a[i] = 0u;
}

// ---------------------------------------------------------------------------
// Iteration 10 (x path only, 2-row coarsened; reads buffer A, writes out).
// ---------------------------------------------------------------------------
__global__ void __launch_bounds__(256)
k_A_last(const float* __restrict__ y, float* __restrict__ outx) {
    const int w = blockIdx.x * 32 + threadIdx.x;
    const int h = (blockIdx.y * 8 + threadIdx.y) * 2;
    const int b = blockIdx.z;
    const int i = (b * HH + h) * WW + w;
    const U2raw* p0 = g_u2a + b * HH * WW + h * WW + w;

    const uint2 w0c = __ldg(p0);
    const uint2 w1c = __ldg(p0 + WW);
    float2 c0xy = bf2unpack(w0c.x), c0zw = bf2unpack(w0c.y);
    float2 c1xy = bf2unpack(w1c.x), c1zw = bf2unpack(w1c.y);
    float2 r0xy = make_float2(0,0), r0zw = r0xy, r1xy = r0xy, r1zw = r0xy;
    if (w < WW - 1) {
        uint2 a = __ldg(p0 + 1), bb2 = __ldg(p0 + WW + 1);
        r0xy = bf2unpack(a.x); r0zw = bf2unpack(a.y);
        r1xy = bf2unpack(bb2.x); r1zw = bf2unpack(bb2.y);
    }
    float2 upzw = make_float2(0,0);
    if (h > 0) upzw = bf2unpack(__ldg(&(p0 - WW)->y));
    float2 l0 = make_float2(0,0), l1 = l0;
    if (w > 0) {
        l0 = bf2unpack(__ldg(&(p0 - 1)->x));
        l1 = bf2unpack(__ldg(&(p0 + WW - 1)->x));
    }
    float Xd1 = 0.f, Xdl1 = 0.f;
    if (h + 2 < HH) {
        Xd1 = bf2unpack(__ldg(&(p0 + 2 * WW)->x)).x;
        if (w > 0) Xdl1 = bf2unpack(__ldg(&(p0 + 2 * WW - 1)->x)).x;
    }
    float Zur0 = 0.f;
    if (h > 0 && w < WW - 1) Zur0 = bf2unpack(__ldg(&(p0 - WW + 1)->y)).x;
    float Wu20 = 0.f;
    if (h >= 2) Wu20 = bf2unpack(__ldg(&(p0 - 2 * WW)->y)).y;

    const float t0p0 = TAUc * (c0xy.x - c1xy.x - r0xy.y + c0xy.y);
    const float t1p0 = TAUc * (c0zw.x - r0zw.x - c0zw.y + upzw.y);
    const float t0l0 = TAUc * (l0.x - l1.x - c0xy.y + l0.y);
    const float t1u0 = TAUc * (upzw.x - Zur0 - upzw.y + Wu20);
    const float t0p1 = TAUc * (c1xy.x - Xd1 - r1xy.y + c1xy.y);
    const float t1p1 = TAUc * (c1zw.x - r1zw.x - c1zw.y + c0zw.y);
    const float t0l1 = TAUc * (l1.x - Xdl1 - c1xy.y + l1.y);

    float dv0 = -t1p0;
    if (w < WW - 1) dv0 -= t0p0;
    if (w > 0)      dv0 += t0l0;
    if (h > 0)      dv0 += t1u0;

    float dv1 = t1p0;
    if (w < WW - 1)  dv1 -= t0p1;
    if (w > 0)       dv1 += t0l1;
    if (h + 2 < HH)  dv1 -= t1p1;

    const float inv = 1.f / (1.f + TAUc);
    const float x2o0 = __ldg(&g_x2a[i]);
    const float x2o1 = __ldg(&g_x2a[i + WW]);
    const float x0 = (x2o0 - dv0 + TAUc * __ldg(&y[i])) * inv;
    const float x1 = (x2o1 - dv1 + TAUc * __ldg(&y[i + WW])) * inv;
    outx[i]      = x2o0 + RHOc * (x0 - x2o0);
    outx[i + WW] = x2o1 + RHOc * (x1 - x2o1);
}

extern "C" void kernel_launch(void* const* d_in, const int* in_sizes, int n_in,
                              void* d_out, int out_size) {
    const float* y   = (const float*)d_in[0];
    const int*   ths = (const int*)d_in[1];
    float*       out = (float*)d_out;

    dim3 blkB(TW, TH, 1);
    dim3 grdB(WW / TW, HH / TH, BB);
    dim3 blkF(32, 8, 1);
    dim3 grdF(WW / 32, HH / 32, BB);
    dim3 blkL(32, 8, 1);
    dim3 grdL(WW / 32, HH / 16, BB);

    // Iteration 1 (closed form) -> buffer A
    k_B_first<<<grdB, blkB>>>(y, ths);

    // Iterations 2..9: fused, ping-pong A<->B (ends in A after 8)
    for (int it = 0; it < 4; ++it) {
        k_F<0><<<grdF, blkF>>>(y, ths);   // A -> B
        k_F<1><<<grdF, blkF>>>(y, ths);   // B -> A
    }

    // Iteration 10: x path only, straight to output (reads A)
    k_A_last<<<grdL, blkL>>>(y, out);
}

// round 13
// speedup vs baseline: 1.3767x; 1.3767x over previous
#include <cuda_runtime.h>
#include <cuda_bf16.h>
#include <math.h>

#define BB 4
#define HH 512
#define WW 512
#define NPIX (BB*HH*WW)
#define TW 32
#define TH 8

#define TAUc   0.01f
#define RHOc   1.99f
#define SIGMAc 1.3888888888888888f   // 1/0.01/72

// u2: 4x bf16 (uint2). r2/rbar: 2x bf16 (u32). x2/xbar: fp32.
typedef uint2 U2raw;
__device__ __align__(16) float    g_x2  [NPIX];
__device__ __align__(16) unsigned g_r2  [NPIX];
__device__ __align__(16) U2raw    g_u2  [NPIX];
__device__ __align__(16) float    g_xbar[NPIX];
__device__ __align__(16) unsigned g_rbar[NPIX];

static __device__ __forceinline__ float4 u2unpack(U2raw r) {
    float2 f0 = __bfloat1622float2(*reinterpret_cast<__nv_bfloat162*>(&r.x));
    float2 f1 = __bfloat1622float2(*reinterpret_cast<__nv_bfloat162*>(&r.y));
    return make_float4(f0.x, f0.y, f1.x, f1.y);
}
static __device__ __forceinline__ float2 bf2unpack(unsigned r) {
    return __bfloat1622float2(*reinterpret_cast<__nv_bfloat162*>(&r));
}
static __device__ __forceinline__ unsigned bf2pack(float a, float b) {
    __nv_bfloat162 p = __floats2bfloat162_rn(a, b);
    return *reinterpret_cast<unsigned*>(&p);
}
static __device__ __forceinline__ U2raw u2pack(float a, float b, float c, float d) {
    U2raw r; r.x = bf2pack(a, b); r.y = bf2pack(c, d); return r;
}

// ---------------------------------------------------------------------------
// Kernel A (R9 2-row coarsened body, PDL-wrapped): prologue loads x2/y/r2/ths
// (written >= 2 launches back -> visible), then waits on the prior k_B before
// touching u2. Trigger after all stores.
// ---------------------------------------------------------------------------
template<bool LAST>
__global__ void __launch_bounds__(256)
k_A(const float* __restrict__ y, const int* __restrict__ ths,
    float* __restrict__ outx) {
    const int w = blockIdx.x * 32 + threadIdx.x;
    const int h = (blockIdx.y * 8 + threadIdx.y) * 2;      // even, <= 510
    const int b = blockIdx.z;
    const int i = (b * HH + h) * WW + w;
    const U2raw* p0 = g_u2 + b * HH * WW + h * WW + w;

    // ---- prologue: independent of the immediately-prior kernel ----
    const float x2o0 = __ldg(&g_x2[i]);
    const float x2o1 = __ldg(&g_x2[i + WW]);
    const float yv0  = __ldg(&y[i]);
    const float yv1  = __ldg(&y[i + WW]);
    unsigned r2w0 = 0u, r2w1 = 0u;
    float lam1 = 1.f;
    if (!LAST) {
        r2w0 = __ldg(&g_r2[i]);
        r2w1 = __ldg(&g_r2[i + WW]);
        lam1 = 0.1f * (float)__ldg(ths);
    }

    cudaGridDependencySynchronize();

    // ---- dependent: u2 (written by prior k_B) ----
    const uint2 w0c = __ldg(p0);
    const uint2 w1c = __ldg(p0 + WW);
    float2 c0xy = bf2unpack(w0c.x), c0zw = bf2unpack(w0c.y);
    float2 c1xy = bf2unpack(w1c.x), c1zw = bf2unpack(w1c.y);
    float2 r0xy = make_float2(0,0), r0zw = r0xy, r1xy = r0xy, r1zw = r0xy;
    if (w < WW - 1) {
        uint2 a = __ldg(p0 + 1), bb2 = __ldg(p0 + WW + 1);
        r0xy = bf2unpack(a.x); r0zw = bf2unpack(a.y);
        r1xy = bf2unpack(bb2.x); r1zw = bf2unpack(bb2.y);
    }
    float2 upzw = make_float2(0,0);
    if (h > 0) upzw = bf2unpack(__ldg(&(p0 - WW)->y));
    float2 l0 = make_float2(0,0), l1 = l0;
    if (w > 0) {
        l0 = bf2unpack(__ldg(&(p0 - 1)->x));
        l1 = bf2unpack(__ldg(&(p0 + WW - 1)->x));
    }
    float Xd1 = 0.f, Xdl1 = 0.f;
    if (h + 2 < HH) {
        Xd1 = bf2unpack(__ldg(&(p0 + 2 * WW)->x)).x;
        if (w > 0) Xdl1 = bf2unpack(__ldg(&(p0 + 2 * WW - 1)->x)).x;
    }
    float Zur0 = 0.f;
    if (h > 0 && w < WW - 1) Zur0 = bf2unpack(__ldg(&(p0 - WW + 1)->y)).x;
    float Wu20 = 0.f;
    if (h >= 2) Wu20 = bf2unpack(__ldg(&(p0 - 2 * WW)->y)).y;

    const float t0p0 = TAUc * (c0xy.x - c1xy.x - r0xy.y + c0xy.y);
    const float t1p0 = TAUc * (c0zw.x - r0zw.x - c0zw.y + upzw.y);
    const float t0l0 = TAUc * (l0.x - l1.x - c0xy.y + l0.y);
    const float t1u0 = TAUc * (upzw.x - Zur0 - upzw.y + Wu20);
    const float t0p1 = TAUc * (c1xy.x - Xd1 - r1xy.y + c1xy.y);
    const float t1p1 = TAUc * (c1zw.x - r1zw.x - c1zw.y + c0zw.y);
    const float t0l1 = TAUc * (l1.x - Xdl1 - c1xy.y + l1.y);

    float dv0 = -t1p0;                  // h < 511 always (h even <= 510)
    if (w < WW - 1) dv0 -= t0p0;
    if (w > 0)      dv0 += t0l0;
    if (h > 0)      dv0 += t1u0;

    float dv1 = t1p0;                   // h+1 > 0 always
    if (w < WW - 1)  dv1 -= t0p1;
    if (w > 0)       dv1 += t0l1;
    if (h + 2 < HH)  dv1 -= t1p1;

    const float inv = 1.f / (1.f + TAUc);
    const float x0 = (x2o0 - dv0 + TAUc * yv0) * inv;
    const float x1 = (x2o1 - dv1 + TAUc * yv1) * inv;
    const float x2n0 = x2o0 + RHOc * (x0 - x2o0);
    const float x2n1 = x2o1 + RHOc * (x1 - x2o1);

    if (LAST) {
        outx[i]      = x2n0;
        outx[i + WW] = x2n1;
        cudaTriggerProgrammaticLaunchCompletion();
        return;
    }

    g_xbar[i]      = 2.f * x0 - x2o0;
    g_xbar[i + WW] = 2.f * x1 - x2o1;
    g_x2[i]        = x2n0;
    g_x2[i + WW]   = x2n1;

    const float itl = 1.f / (TAUc * lam1);
    {
        const float2 o = bf2unpack(r2w0);
        const float rvx = o.x + t0p0, rvy = o.y + t1p0;
        const float s = 1.f - 1.f / fmaxf(sqrtf(rvx*rvx + rvy*rvy) * itl, 1.f);
        const float rx = rvx * s, ry = rvy * s;
        g_rbar[i] = bf2pack(2.f * rx - o.x, 2.f * ry - o.y);
        g_r2[i]   = bf2pack(o.x + RHOc * (rx - o.x), o.y + RHOc * (ry - o.y));
    }
    {
        const float2 o = bf2unpack(r2w1);
        const float rvx = o.x + t0p1, rvy = o.y + t1p1;
        const float s = 1.f - 1.f / fmaxf(sqrtf(rvx*rvx + rvy*rvy) * itl, 1.f);
        const float rx = rvx * s, ry = rvy * s;
        g_rbar[i + WW] = bf2pack(2.f * rx - o.x, 2.f * ry - o.y);
        g_r2[i + WW]   = bf2pack(o.x + RHOc * (rx - o.x), o.y + RHOc * (ry - o.y));
    }
    cudaTriggerProgrammaticLaunchCompletion();
}

// ---------------------------------------------------------------------------
// Kernel B (R8/R9 body, PDL-wrapped): prologue loads its center u2 + ths
// (written by the k_B two launches back -> visible), waits before xbar/rbar.
// FIRST iteration: xbar == y, rbar == 0, u2 == 0; also initializes x2=y, r2=0.
// ---------------------------------------------------------------------------
template<bool FIRST>
__global__ void __launch_bounds__(TW*TH)
k_B(const float* __restrict__ y, const int* __restrict__ ths) {
    __shared__ float  sx[TH + 3][TW + 3];
    __shared__ float2 sv[TH + 2][TW + 2];

    const int tx = threadIdx.x, ty = threadIdx.y;
    const int tid = ty * TW + tx;
    const int w0 = blockIdx.x * TW, h0 = blockIdx.y * TH, b = blockIdx.z;
    const int boff = b * HH * WW;
    const float* xb = FIRST ? (y + boff) : (g_xbar + boff);

    const int h = h0 + ty, w = w0 + tx;
    const int i = boff + h * WW + w;

    // ---- prologue ----
    float4 u2o = make_float4(0.f, 0.f, 0.f, 0.f);
    if (!FIRST) u2o = u2unpack(__ldg(&g_u2[i]));
    const float lam2 = 0.15f * (float)__ldg(ths);

    cudaGridDependencySynchronize();

    // ---- dependent: xbar/rbar from the prior k_A ----
    #pragma unroll
    for (int idx = tid; idx < (TH + 3) * (TW + 2); idx += TW * TH) {
        int rr = idx / (TW + 2), cc = idx % (TW + 2);
        int gh = h0 + rr - 1, gw = w0 + cc - 1;
        float v = 0.f;
        if (gh >= 0 && gh < HH && gw >= 0 && gw < WW) v = __ldg(xb + gh * WW + gw);
        sx[rr][cc] = v;
    }
    __syncthreads();

    #pragma unroll
    for (int idx = tid; idx < (TH + 2) * (TW + 1); idx += TW * TH) {
        int R = idx / (TW + 1), C = idx % (TW + 1);
        int gh = h0 + R - 1, gw = w0 + C - 1;
        float2 v = make_float2(0.f, 0.f);
        if (gh >= 0 && gh < HH && gw >= 0 && gw < WW) {
            float xc = sx[R][C];
            float v0 = (gw < WW - 1) ? (sx[R][C + 1] - xc) : 0.f;
            float v1 = (gh < HH - 1) ? (sx[R + 1][C] - xc) : 0.f;
            if (!FIRST) {
                float2 rb = bf2unpack(__ldg(&g_rbar[boff + gh * WW + gw]));
                v0 -= rb.x; v1 -= rb.y;
            }
            v = make_float2(v0, v1);
        }
        sv[R][C] = v;
    }
    __syncthreads();

    float2 vc = sv[ty + 1][tx + 1];
    float2 vu = sv[ty][tx + 1];
    float2 vl = sv[ty + 1][tx];
    float2 vd = sv[ty + 2][tx + 1];

    float G0 = vc.x - vu.x;
    float G1 = (w > 0) ? (vc.x - vl.x) : 0.f;
    float G2 = vc.y - vl.y;
    float G3 = (h < HH - 1) ? (vd.y - vc.y) : 0.f;

    float u0 = u2o.x + SIGMAc * G0;
    float u1 = u2o.y + SIGMAc * G1;
    float u2c = u2o.z + SIGMAc * G2;
    float u3 = u2o.w + SIGMAc * G3;

    float nrm = sqrtf(u0 * u0 + u1 * u1 + u2c * u2c + u3 * u3);
    float sc = 1.f / fmaxf(nrm * (1.f / lam2), 1.f);
    u0 *= sc; u1 *= sc; u2c *= sc; u3 *= sc;

    g_u2[i] = u2pack(u2o.x + RHOc * (u0  - u2o.x),
                     u2o.y + RHOc * (u1  - u2o.y),
                     u2o.z + RHOc * (u2c - u2o.z),
                     u2o.w + RHOc * (u3  - u2o.w));

    if (FIRST) {
        g_x2[i] = sx[ty + 1][tx + 1];
        g_r2[i] = 0u;
    }
    cudaTriggerProgrammaticLaunchCompletion();
}

// ---------------------------------------------------------------------------
// Host side: PDL launches on the default (capture) stream.
// ---------------------------------------------------------------------------
template<typename F>
static void launch_pdl(F* fn, dim3 g, dim3 blk,
                       const float* y, const int* ths, float* out,
                       bool has_out) {
    cudaLaunchConfig_t cfg = {};
    cfg.gridDim = g;
    cfg.blockDim = blk;
    cfg.dynamicSmemBytes = 0;
    cfg.stream = 0;
    cudaLaunchAttribute attr[1];
    attr[0].id = cudaLaunchAttributeProgrammaticStreamSerialization;
    attr[0].val.programmaticStreamSerializationAllowed = 1;
    cfg.attrs = attr;
    cfg.numAttrs = 1;
    (void)has_out;
    cudaLaunchKernelEx(&cfg, fn, y, ths, out);
}

static void launch_pdl_B(void (*fn)(const float*, const int*), dim3 g, dim3 blk,
                         const float* y, const int* ths) {
    cudaLaunchConfig_t cfg = {};
    cfg.gridDim = g;
    cfg.blockDim = blk;
    cfg.dynamicSmemBytes = 0;
    cfg.stream = 0;
    cudaLaunchAttribute attr[1];
    attr[0].id = cudaLaunchAttributeProgrammaticStreamSerialization;
    attr[0].val.programmaticStreamSerializationAllowed = 1;
    cfg.attrs = attr;
    cfg.numAttrs = 1;
    cudaLaunchKernelEx(&cfg, fn, y, ths);
}

extern "C" void kernel_launch(void* const* d_in, const int* in_sizes, int n_in,
                              void* d_out, int out_size) {
    const float* y   = (const float*)d_in[0];
    const int*   ths = (const int*)d_in[1];
    float*       out = (float*)d_out;

    dim3 blkA(32, 8, 1);
    dim3 grdA(WW / 32, HH / 16, BB);     // 2 rows per thread
    dim3 blkB(TW, TH, 1);
    dim3 grdB(WW / TW, HH / TH, BB);

    // Iteration 1 (specialized: A is a no-op closed form)
    launch_pdl_B(k_B<true>, grdB, blkB, y, ths);

    // Iterations 2..9
    for (int it = 1; it < 9; ++it) {
        launch_pdl(k_A<false>, grdA, blkA, y, ths, (float*)nullptr, false);
        launch_pdl_B(k_B<false>, grdB, blkB, y, ths);
    }

    // Iteration 10: only the x path matters; write straight to output.
    launch_pdl(k_A<true>, grdA, blkA, y, ths, out, true);
}

// round 14
// speedup vs baseline: 1.5163x; 1.1014x over previous
#include <cuda_runtime.h>
#include <cuda_bf16.h>
#include <math.h>

#define BB 4
#define HH 512
#define WW 512
#define NPIX (BB*HH*WW)
#define TW 32
#define TH 8

#define TAUc   0.01f
#define RHOc   1.99f
#define SIGMAc 1.3888888888888888f   // 1/0.01/72

// Packed state:
//   g_s  [i] = { x2 (fp32 bits),  r2  (bf16x2) }
//   g_xr [i] = { xbar (fp32 bits), rbar (bf16x2) }
//   g_u2 [i] = u2 as 4x bf16 (uint2)
typedef uint2 U2raw;
__device__ __align__(16) uint2 g_s [NPIX];
__device__ __align__(16) uint2 g_xr[NPIX];
__device__ __align__(16) U2raw g_u2[NPIX];

static __device__ __forceinline__ float4 u2unpack(U2raw r) {
    float2 f0 = __bfloat1622float2(*reinterpret_cast<__nv_bfloat162*>(&r.x));
    float2 f1 = __bfloat1622float2(*reinterpret_cast<__nv_bfloat162*>(&r.y));
    return make_float4(f0.x, f0.y, f1.x, f1.y);
}
static __device__ __forceinline__ float2 bf2unpack(unsigned r) {
    return __bfloat1622float2(*reinterpret_cast<__nv_bfloat162*>(&r));
}
static __device__ __forceinline__ unsigned bf2pack(float a, float b) {
    __nv_bfloat162 p = __floats2bfloat162_rn(a, b);
    return *reinterpret_cast<unsigned*>(&p);
}
static __device__ __forceinline__ U2raw u2pack(float a, float b, float c, float d) {
    U2raw r; r.x = bf2pack(a, b); r.y = bf2pack(c, d); return r;
}

// ---------------------------------------------------------------------------
// Kernel A (2-row coarsened, packed state, PDL): prologue loads g_s/y/ths
// (written >= 2 launches back -> transitively visible), waits, then u2.
// ---------------------------------------------------------------------------
template<bool LAST>
__global__ void __launch_bounds__(256)
k_A(const float* __restrict__ y, const int* __restrict__ ths,
    float* __restrict__ outx) {
    const int w = blockIdx.x * 32 + threadIdx.x;
    const int h = (blockIdx.y * 8 + threadIdx.y) * 2;      // even, <= 510
    const int b = blockIdx.z;
    const int i = (b * HH + h) * WW + w;
    const U2raw* p0 = g_u2 + b * HH * WW + h * WW + w;

    // ---- prologue: independent of the immediately-prior kernel ----
    const uint2 s0 = __ldg(&g_s[i]);
    const uint2 s1 = __ldg(&g_s[i + WW]);
    const float x2o0 = __uint_as_float(s0.x);
    const float x2o1 = __uint_as_float(s1.x);
    const float yv0  = __ldg(&y[i]);
    const float yv1  = __ldg(&y[i + WW]);
    float lam1 = 1.f;
    if (!LAST) lam1 = 0.1f * (float)__ldg(ths);

    cudaGridDependencySynchronize();

    // ---- dependent: u2 (written by prior k_B) ----
    const uint2 w0c = __ldg(p0);
    const uint2 w1c = __ldg(p0 + WW);
    float2 c0xy = bf2unpack(w0c.x), c0zw = bf2unpack(w0c.y);
    float2 c1xy = bf2unpack(w1c.x), c1zw = bf2unpack(w1c.y);
    float2 r0xy = make_float2(0,0), r0zw = r0xy, r1xy = r0xy, r1zw = r0xy;
    if (w < WW - 1) {
        uint2 a = __ldg(p0 + 1), bb2 = __ldg(p0 + WW + 1);
        r0xy = bf2unpack(a.x); r0zw = bf2unpack(a.y);
        r1xy = bf2unpack(bb2.x); r1zw = bf2unpack(bb2.y);
    }
    float2 upzw = make_float2(0,0);
    if (h > 0) upzw = bf2unpack(__ldg(&(p0 - WW)->y));
    float2 l0 = make_float2(0,0), l1 = l0;
    if (w > 0) {
        l0 = bf2unpack(__ldg(&(p0 - 1)->x));
        l1 = bf2unpack(__ldg(&(p0 + WW - 1)->x));
    }
    float Xd1 = 0.f, Xdl1 = 0.f;
    if (h + 2 < HH) {
        Xd1 = bf2unpack(__ldg(&(p0 + 2 * WW)->x)).x;
        if (w > 0) Xdl1 = bf2unpack(__ldg(&(p0 + 2 * WW - 1)->x)).x;
    }
    float Zur0 = 0.f;
    if (h > 0 && w < WW - 1) Zur0 = bf2unpack(__ldg(&(p0 - WW + 1)->y)).x;
    float Wu20 = 0.f;
    if (h >= 2) Wu20 = bf2unpack(__ldg(&(p0 - 2 * WW)->y)).y;

    const float t0p0 = TAUc * (c0xy.x - c1xy.x - r0xy.y + c0xy.y);
    const float t1p0 = TAUc * (c0zw.x - r0zw.x - c0zw.y + upzw.y);
    const float t0l0 = TAUc * (l0.x - l1.x - c0xy.y + l0.y);
    const float t1u0 = TAUc * (upzw.x - Zur0 - upzw.y + Wu20);
    const float t0p1 = TAUc * (c1xy.x - Xd1 - r1xy.y + c1xy.y);
    const float t1p1 = TAUc * (c1zw.x - r1zw.x - c1zw.y + c0zw.y);
    const float t0l1 = TAUc * (l1.x - Xdl1 - c1xy.y + l1.y);

    float dv0 = -t1p0;                  // h < 511 always (h even <= 510)
    if (w < WW - 1) dv0 -= t0p0;
    if (w > 0)      dv0 += t0l0;
    if (h > 0)      dv0 += t1u0;

    float dv1 = t1p0;                   // h+1 > 0 always
    if (w < WW - 1)  dv1 -= t0p1;
    if (w > 0)       dv1 += t0l1;
    if (h + 2 < HH)  dv1 -= t1p1;

    const float inv = 1.f / (1.f + TAUc);
    const float x0 = (x2o0 - dv0 + TAUc * yv0) * inv;
    const float x1 = (x2o1 - dv1 + TAUc * yv1) * inv;
    const float x2n0 = x2o0 + RHOc * (x0 - x2o0);
    const float x2n1 = x2o1 + RHOc * (x1 - x2o1);

    if (LAST) {
        outx[i]      = x2n0;
        outx[i + WW] = x2n1;
        cudaTriggerProgrammaticLaunchCompletion();
        return;
    }

    const float itl = 1.f / (TAUc * lam1);
    uint2 xr0, xr1, sn0, sn1;
    xr0.x = __float_as_uint(2.f * x0 - x2o0);
    xr1.x = __float_as_uint(2.f * x1 - x2o1);
    sn0.x = __float_as_uint(x2n0);
    sn1.x = __float_as_uint(x2n1);
    {
        const float2 o = bf2unpack(s0.y);
        const float rvx = o.x + t0p0, rvy = o.y + t1p0;
        const float s = 1.f - 1.f / fmaxf(sqrtf(rvx*rvx + rvy*rvy) * itl, 1.f);
        const float rx = rvx * s, ry = rvy * s;
        xr0.y = bf2pack(2.f * rx - o.x, 2.f * ry - o.y);
        sn0.y = bf2pack(o.x + RHOc * (rx - o.x), o.y + RHOc * (ry - o.y));
    }
    {
        const float2 o = bf2unpack(s1.y);
        const float rvx = o.x + t0p1, rvy = o.y + t1p1;
        const float s = 1.f - 1.f / fmaxf(sqrtf(rvx*rvx + rvy*rvy) * itl, 1.f);
        const float rx = rvx * s, ry = rvy * s;
        xr1.y = bf2pack(2.f * rx - o.x, 2.f * ry - o.y);
        sn1.y = bf2pack(o.x + RHOc * (rx - o.x), o.y + RHOc * (ry - o.y));
    }
    g_xr[i]      = xr0;
    g_xr[i + WW] = xr1;
    g_s[i]       = sn0;
    g_s[i + WW]  = sn1;
    cudaTriggerProgrammaticLaunchCompletion();
}

// ---------------------------------------------------------------------------
// Kernel B (PDL, packed xbar/rbar): one packed halo load feeds both the
// nabla2(xbar) stencil and the rbar subtraction. FIRST: xbar==y, rbar==0,
// u2==0; also initializes g_s = (y, 0).
// ---------------------------------------------------------------------------
template<bool FIRST>
__global__ void __launch_bounds__(TW*TH)
k_B(const float* __restrict__ y, const int* __restrict__ ths) {
    __shared__ float    sx [TH + 3][TW + 3];
    __shared__ unsigned srb[TH + 3][TW + 2];
    __shared__ float2   sv [TH + 2][TW + 2];

    const int tx = threadIdx.x, ty = threadIdx.y;
    const int tid = ty * TW + tx;
    const int w0 = blockIdx.x * TW, h0 = blockIdx.y * TH, b = blockIdx.z;
    const int boff = b * HH * WW;

    const int h = h0 + ty, w = w0 + tx;
    const int i = boff + h * WW + w;

    // ---- prologue ----
    float4 u2o = make_float4(0.f, 0.f, 0.f, 0.f);
    if (!FIRST) u2o = u2unpack(__ldg(&g_u2[i]));
    const float lam2 = 0.15f * (float)__ldg(ths);

    cudaGridDependencySynchronize();

    // ---- dependent: packed xbar/rbar halo (from prior k_A) ----
    #pragma unroll
    for (int idx = tid; idx < (TH + 3) * (TW + 2); idx += TW * TH) {
        int rr = idx / (TW + 2), cc = idx % (TW + 2);
        int gh = h0 + rr - 1, gw = w0 + cc - 1;
        float xv = 0.f;
        unsigned rb = 0u;
        if (gh >= 0 && gh < HH && gw >= 0 && gw < WW) {
            if (FIRST) {
                xv = __ldg(&y[boff + gh * WW + gw]);
            } else {
                uint2 pw = __ldg(&g_xr[boff + gh * WW + gw]);
                xv = __uint_as_float(pw.x);
                rb = pw.y;
            }
        }
        sx[rr][cc]  = xv;
        srb[rr][cc] = rb;
    }
    __syncthreads();

    #pragma unroll
    for (int idx = tid; idx < (TH + 2) * (TW + 1); idx += TW * TH) {
        int R = idx / (TW + 1), C = idx % (TW + 1);
        int gh = h0 + R - 1, gw = w0 + C - 1;
        float2 v = make_float2(0.f, 0.f);
        if (gh >= 0 && gh < HH && gw >= 0 && gw < WW) {
            float xc = sx[R][C];
            float v0 = (gw < WW - 1) ? (sx[R][C + 1] - xc) : 0.f;
            float v1 = (gh < HH - 1) ? (sx[R + 1][C] - xc) : 0.f;
            float2 rb = bf2unpack(srb[R][C]);
            v = make_float2(v0 - rb.x, v1 - rb.y);
        }
        sv[R][C] = v;
    }
    __syncthreads();

    float2 vc = sv[ty + 1][tx + 1];
    float2 vu = sv[ty][tx + 1];
    float2 vl = sv[ty + 1][tx];
    float2 vd = sv[ty + 2][tx + 1];

    float G0 = vc.x - vu.x;
    float G1 = (w > 0) ? (vc.x - vl.x) : 0.f;
    float G2 = vc.y - vl.y;
    float G3 = (h < HH - 1) ? (vd.y - vc.y) : 0.f;

    float u0 = u2o.x + SIGMAc * G0;
    float u1 = u2o.y + SIGMAc * G1;
    float u2c = u2o.z + SIGMAc * G2;
    float u3 = u2o.w + SIGMAc * G3;

    float nrm = sqrtf(u0 * u0 + u1 * u1 + u2c * u2c + u3 * u3);
    float sc = 1.f / fmaxf(nrm * (1.f / lam2), 1.f);
    u0 *= sc; u1 *= sc; u2c *= sc; u3 *= sc;

    g_u2[i] = u2pack(u2o.x + RHOc * (u0  - u2o.x),
                     u2o.y + RHOc * (u1  - u2o.y),
                     u2o.z + RHOc * (u2c - u2o.z),
                     u2o.w + RHOc * (u3  - u2o.w));

    if (FIRST) {
        uint2 s;
        s.x = __float_as_uint(sx[ty + 1][tx + 1]);
        s.y = 0u;
        g_s[i] = s;
    }
    cudaTriggerProgrammaticLaunchCompletion();
}

// ---------------------------------------------------------------------------
// Host side: PDL launches on the default (capture) stream.
// ---------------------------------------------------------------------------
static void launch_pdl_A(void (*fn)(const float*, const int*, float*),
                         dim3 g, dim3 blk,
                         const float* y, const int* ths, float* out) {
    cudaLaunchConfig_t cfg = {};
    cfg.gridDim = g;
    cfg.blockDim = blk;
    cfg.dynamicSmemBytes = 0;
    cfg.stream = 0;
    cudaLaunchAttribute attr[1];
    attr[0].id = cudaLaunchAttributeProgrammaticStreamSerialization;
    attr[0].val.programmaticStreamSerializationAllowed = 1;
    cfg.attrs = attr;
    cfg.numAttrs = 1;
    cudaLaunchKernelEx(&cfg, fn, y, ths, out);
}
static void launch_pdl_B(void (*fn)(const float*, const int*), dim3 g, dim3 blk,
                         const float* y, const int* ths) {
    cudaLaunchConfig_t cfg = {};
    cfg.gridDim = g;
    cfg.blockDim = blk;
    cfg.dynamicSmemBytes = 0;
    cfg.stream = 0;
    cudaLaunchAttribute attr[1];
    attr[0].id = cudaLaunchAttributeProgrammaticStreamSerialization;
    attr[0].val.programmaticStreamSerializationAllowed = 1;
    cfg.attrs = attr;
    cfg.numAttrs = 1;
    cudaLaunchKernelEx(&cfg, fn, y, ths);
}

extern "C" void kernel_launch(void* const* d_in, const int* in_sizes, int n_in,
                              void* d_out, int out_size) {
    const float* y   = (const float*)d_in[0];
    const int*   ths = (const int*)d_in[1];
    float*       out = (float*)d_out;

    dim3 blkA(32, 8, 1);
    dim3 grdA(WW / 32, HH / 16, BB);     // 2 rows per thread
    dim3 blkB(TW, TH, 1);
    dim3 grdB(WW / TW, HH / TH, BB);

    // Iteration 1 (specialized: A is a no-op closed form)
    launch_pdl_B(k_B<true>, grdB, blkB, y, ths);

    // Iterations 2..9
    for (int it = 1; it < 9; ++it) {
        launch_pdl_A(k_A<false>, grdA, blkA, y, ths, nullptr);
        launch_pdl_B(k_B<false>, grdB, blkB, y, ths);
    }

    // Iteration 10: only the x path matters; write straight to output.
    launch_pdl_A(k_A<true>, grdA, blkA, y, ths, out);
}